// round 13
// baseline (speedup 1.0000x reference)
#include <cuda_runtime.h>
#include <cuda_fp16.h>
#include <cstdint>
#include <math.h>

// ===================== problem constants =====================
constexpr int Bsz = 2;
constexpr int Hn  = 16;
constexpr int Sn  = 2048;
constexpr int Dh  = 128;

constexpr int BQ = 64;    // q rows per CTA (4 warps x 16 rows)
constexpr int BK = 64;    // k cols per iteration
constexpr int NT = 128;   // 4 warps
constexpr int NTILES = Sn / 64;   // 32 tiles of 64 rows
constexpr int NBH = Bsz * Hn;     // 32

constexpr int RSB = 272;  // row stride in bytes (136 fp16) -> conflict-free ldmatrix
constexpr int TILE1 = 64 * RSB;       // one 64x128 fp16 tile, padded: 17408 B
constexpr int TILEB = 2 * TILE1;      // hi + lo pair: 34816 B

// smem: Q (hi+lo) | Khi | shared buf (Klo then V) | am
constexpr int SM_Q   = 0;
constexpr int SM_KHI = SM_Q + TILEB;      // 34816
constexpr int SM_B3  = SM_KHI + TILE1;    // 52224 (Klo during QK, V during PV)
constexpr int SM_AM  = SM_B3 + TILE1;     // 69632
constexpr int SM_TOTAL = SM_AM + BK * 4;  // 69888 B

constexpr float LOG2E = 1.4426950408889634f;

// ===================== device scratch (converted tiles, padded layout) =====================
__device__ __align__(16) unsigned char g_k[NBH][NTILES][TILEB];   // hi at 0, lo at +TILE1
__device__ __align__(16) unsigned char g_v[NBH][NTILES][TILE1];   // hi only

// ===================== helpers =====================
static __device__ __forceinline__ uint32_t smem_u32(const void* p) {
    uint32_t a;
    asm("{ .reg .u64 t; cvta.to.shared.u64 t, %1; cvt.u32.u64 %0, t; }" : "=r"(a) : "l"(p));
    return a;
}
static __device__ __forceinline__ void ldsm4(uint32_t* r, uint32_t a) {
    asm volatile("ldmatrix.sync.aligned.m8n8.x4.shared.b16 {%0,%1,%2,%3}, [%4];"
                 : "=r"(r[0]), "=r"(r[1]), "=r"(r[2]), "=r"(r[3]) : "r"(a));
}
static __device__ __forceinline__ void ldsm4t(uint32_t* r, uint32_t a) {
    asm volatile("ldmatrix.sync.aligned.m8n8.x4.trans.shared.b16 {%0,%1,%2,%3}, [%4];"
                 : "=r"(r[0]), "=r"(r[1]), "=r"(r[2]), "=r"(r[3]) : "r"(a));
}
static __device__ __forceinline__ void mma_f16(float* c, const uint32_t* a, const uint32_t* b) {
    asm volatile("mma.sync.aligned.m16n8k16.row.col.f32.f16.f16.f32 "
                 "{%0,%1,%2,%3},{%4,%5,%6,%7},{%8,%9},{%0,%1,%2,%3};"
                 : "+f"(c[0]), "+f"(c[1]), "+f"(c[2]), "+f"(c[3])
                 : "r"(a[0]), "r"(a[1]), "r"(a[2]), "r"(a[3]), "r"(b[0]), "r"(b[1]));
}
// fp16-accumulator MMA (2x throughput) for small correction terms
static __device__ __forceinline__ void mma_h16(uint32_t* c, const uint32_t* a, const uint32_t* b) {
    asm volatile("mma.sync.aligned.m16n8k16.row.col.f16.f16.f16.f16 "
                 "{%0,%1},{%2,%3,%4,%5},{%6,%7},{%0,%1};"
                 : "+r"(c[0]), "+r"(c[1])
                 : "r"(a[0]), "r"(a[1]), "r"(a[2]), "r"(a[3]), "r"(b[0]), "r"(b[1]));
}
static __device__ __forceinline__ uint32_t cvt2h(float lo, float hi) {
    uint32_t r;
    asm("cvt.rn.f16x2.f32 %0, %1, %2;" : "=r"(r) : "f"(hi), "f"(lo));
    return r;
}
static __device__ __forceinline__ float2 h2f2(uint32_t u) {
    __half2 h = *reinterpret_cast<__half2*>(&u);
    return __half22float2(h);
}
static __device__ __forceinline__ float ex2f(float x) {
    float r;
    asm("ex2.approx.ftz.f32 %0, %1;" : "=f"(r) : "f"(x));
    return r;
}

#define CP16(s, g) \
    asm volatile("cp.async.cg.shared.global [%0], [%1], 16;" :: "r"(s), "l"(g) : "memory")
#define CP_COMMIT() asm volatile("cp.async.commit_group;" ::: "memory")
#define CP_WAIT0()  asm volatile("cp.async.wait_group 0;"  ::: "memory")

// async copy one 17408-B tile; 8.5 chunks/thread
static __device__ __forceinline__ void copy17(uint32_t sdst,
                                              const unsigned char* gsrc, int tid) {
    unsigned long long ga = (unsigned long long)__cvta_generic_to_global((void*)gsrc);
    #pragma unroll
    for (int it = 0; it < 8; ++it) {
        int c = (it * NT + tid) * 16;
        CP16(sdst + c, ga + c);
    }
    if (tid < 64) {                       // remaining 1024 B
        int c = (8 * NT + tid) * 16;
        CP16(sdst + c, ga + c);
    }
}

// fp32 -> fp16 hi/lo pair (padded layout), 128 threads
template <bool SCALE>
static __device__ __forceinline__ void conv_pair(const float* __restrict__ g,
                                                 unsigned char* dst, int tid) {
    #pragma unroll
    for (int it = 0; it < 8; ++it) {
        int e = it * 128 + tid;                // 1024 chunks of 8 floats
        int row = e >> 4, c8 = e & 15;
        const float4* src = reinterpret_cast<const float4*>(g) + 2 * e;
        float4 x = src[0], y = src[1];
        if (SCALE) {
            x.x *= LOG2E; x.y *= LOG2E; x.z *= LOG2E; x.w *= LOG2E;
            y.x *= LOG2E; y.y *= LOG2E; y.z *= LOG2E; y.w *= LOG2E;
        }
        uint32_t h0 = cvt2h(x.x, x.y), h1 = cvt2h(x.z, x.w);
        uint32_t h2 = cvt2h(y.x, y.y), h3 = cvt2h(y.z, y.w);
        float2 f0 = h2f2(h0), f1 = h2f2(h1), f2 = h2f2(h2), f3 = h2f2(h3);
        uint32_t l0 = cvt2h(x.x - f0.x, x.y - f0.y);
        uint32_t l1 = cvt2h(x.z - f1.x, x.w - f1.y);
        uint32_t l2 = cvt2h(y.x - f2.x, y.y - f2.y);
        uint32_t l3 = cvt2h(y.z - f3.x, y.w - f3.y);
        int off = row * RSB + c8 * 16;
        *reinterpret_cast<uint4*>(dst + off)         = make_uint4(h0, h1, h2, h3);
        *reinterpret_cast<uint4*>(dst + TILE1 + off) = make_uint4(l0, l1, l2, l3);
    }
}
static __device__ __forceinline__ void conv_hi(const float* __restrict__ g,
                                               unsigned char* dst, int tid) {
    #pragma unroll
    for (int it = 0; it < 8; ++it) {
        int e = it * 128 + tid;
        int row = e >> 4, c8 = e & 15;
        const float4* src = reinterpret_cast<const float4*>(g) + 2 * e;
        float4 x = src[0], y = src[1];
        uint32_t h0 = cvt2h(x.x, x.y), h1 = cvt2h(x.z, x.w);
        uint32_t h2 = cvt2h(y.x, y.y), h3 = cvt2h(y.z, y.w);
        int off = row * RSB + c8 * 16;
        *reinterpret_cast<uint4*>(dst + off) = make_uint4(h0, h1, h2, h3);
    }
}

// ===================== prepass: K (hi+lo), V (hi) only =====================
__global__ __launch_bounds__(128)
void prep_kernel(const float* __restrict__ k, const float* __restrict__ v)
{
    const int kt = blockIdx.x, bh = blockIdx.y, tid = threadIdx.x;
    const size_t base = ((size_t)bh * Sn + (size_t)kt * 64) * Dh;
    conv_pair<false>(k + base, &g_k[bh][kt][0], tid);
    conv_hi(v + base, &g_v[bh][kt][0], tid);
}

// ===================== main kernel =====================
__global__ __launch_bounds__(NT, 2)
void fa_mma_kernel(const float* __restrict__ q, const float* __restrict__ am,
                   const float* __restrict__ hm, float* __restrict__ out)
{
    extern __shared__ char smem[];
    const uint32_t sbase = smem_u32(smem);
    float* am_s = reinterpret_cast<float*>(smem + SM_AM);

    const int tid = threadIdx.x, wid = tid >> 5, lane = tid & 31;
    const int bh = blockIdx.y, b = bh >> 4, h = bh & 15;
    const int qt = (int)gridDim.x - 1 - (int)blockIdx.x;   // heavy tiles first
    const int q0 = qt * BQ;
    const int nkt = qt + 1;                                // BQ == BK

    const float* amg = am + (size_t)b * Sn;
    const float  hmv = hm[h];

    // ---- prologue: issue K(0) cp.async, then convert Q (overlaps) ----
    copy17(sbase + SM_KHI, &g_k[bh][0][0], tid);
    copy17(sbase + SM_B3,  &g_k[bh][0][TILE1], tid);
    CP_COMMIT();
    conv_pair<true>(q + ((size_t)bh * Sn + q0) * Dh, (unsigned char*)smem + SM_Q, tid);

    // per-lane ldmatrix base addresses
    const int m0 = wid * 16;
    const uint32_t qoff = sbase + SM_Q + (m0 + (lane & 15)) * RSB + ((lane >> 4) & 1) * 16;
    const uint32_t koff = sbase + SM_KHI + ((lane & 7) + ((lane >> 4) & 1) * 8) * RSB + ((lane >> 3) & 1) * 16;
    const uint32_t voff = sbase + SM_B3 + ((lane & 7) + ((lane >> 3) & 1) * 8) * RSB + ((lane >> 4) & 1) * 16;
    constexpr int DKL = SM_B3 - SM_KHI;   // Klo offset relative to Khi

    float o[64];
    #pragma unroll
    for (int i = 0; i < 64; ++i) o[i] = 0.0f;
    float M0 = -INFINITY, M1 = -INFINITY, L0 = 0.0f, L1 = 0.0f;

    const int rg0 = q0 + m0 + (lane >> 2);   // global q row (upper)
    const int rg1 = rg0 + 8;
    const int c00 = 2 * (lane & 3);          // local col base within n8 tile

    for (int kt = 0; kt < nkt; ++kt) {
        // ---- wait for K(kt) (Klo in B3); Q STS ordered by this sync too ----
        CP_WAIT0();
        __syncthreads();
        if (tid < BK) am_s[tid] = amg[kt * BK + tid] * LOG2E;   // read after post-QK sync

        // ---- S' = log2e * Q K^T ----
        //   hi*hi in fp32 accum; (Qhi*Klo + Qlo*Khi) corrections in fp16 accum (2x rate)
        float sv[32];
        #pragma unroll
        for (int i = 0; i < 32; ++i) sv[i] = 0.0f;
        uint32_t cc[16];
        #pragma unroll
        for (int i = 0; i < 16; ++i) cc[i] = 0u;

        #pragma unroll
        for (int t = 0; t < 8; ++t) {                 // k16 tiles over d=128
            uint32_t ah[4], al[4];
            ldsm4(ah, qoff + t * 32);
            ldsm4(al, qoff + TILE1 + t * 32);
            #pragma unroll
            for (int g = 0; g < 4; ++g) {             // n16 groups over 64 cols
                uint32_t bh4[4], bl4[4];
                ldsm4(bh4, koff + g * (16 * RSB) + t * 32);
                ldsm4(bl4, koff + DKL + g * (16 * RSB) + t * 32);
                mma_f16(sv + 8 * g,     ah, bh4);       // hi*hi (fp32 acc)
                mma_f16(sv + 8 * g + 4, ah, bh4 + 2);
                mma_h16(cc + 4 * g,     ah, bl4);       // corrections (fp16 acc)
                mma_h16(cc + 4 * g + 2, ah, bl4 + 2);
                mma_h16(cc + 4 * g,     al, bh4);
                mma_h16(cc + 4 * g + 2, al, bh4 + 2);
            }
        }
        // fold fp16 corrections into sv
        #pragma unroll
        for (int g = 0; g < 4; ++g) {
            float2 x0 = h2f2(cc[4 * g + 0]), x1 = h2f2(cc[4 * g + 1]);
            float2 x2 = h2f2(cc[4 * g + 2]), x3 = h2f2(cc[4 * g + 3]);
            sv[8*g+0] += x0.x;  sv[8*g+1] += x0.y;
            sv[8*g+2] += x1.x;  sv[8*g+3] += x1.y;
            sv[8*g+4] += x2.x;  sv[8*g+5] += x2.y;
            sv[8*g+6] += x3.x;  sv[8*g+7] += x3.y;
        }

        // ---- K(kt) dead: bring V(kt) into B3, Khi(kt+1) into KHI ----
        __syncthreads();
        copy17(sbase + SM_B3, &g_v[bh][kt][0], tid);
        if (kt + 1 < nkt) copy17(sbase + SM_KHI, &g_k[bh][kt + 1][0], tid);
        CP_COMMIT();

        // ---- causal mask + additive attn_mask (log2 domain) ----
        float amr[16];
        #pragma unroll
        for (int n = 0; n < 8; ++n) {
            float2 a2 = *reinterpret_cast<const float2*>(&am_s[8 * n + c00]);
            amr[2 * n] = a2.x; amr[2 * n + 1] = a2.y;
        }
        if (kt == nkt - 1) {   // only the diagonal tile needs element checks
            #pragma unroll
            for (int n = 0; n < 8; ++n) {
                int cg = kt * BK + 8 * n + c00;
                sv[4*n+0] = (cg     <= rg0) ? sv[4*n+0] + amr[2*n]   : -1e30f;
                sv[4*n+1] = (cg + 1 <= rg0) ? sv[4*n+1] + amr[2*n+1] : -1e30f;
                sv[4*n+2] = (cg     <= rg1) ? sv[4*n+2] + amr[2*n]   : -1e30f;
                sv[4*n+3] = (cg + 1 <= rg1) ? sv[4*n+3] + amr[2*n+1] : -1e30f;
            }
        } else {
            #pragma unroll
            for (int n = 0; n < 8; ++n) {
                sv[4*n+0] += amr[2*n];   sv[4*n+1] += amr[2*n+1];
                sv[4*n+2] += amr[2*n];   sv[4*n+3] += amr[2*n+1];
            }
        }

        // ---- online softmax in base-2 domain (overlaps V copy) ----
        float t0 = -INFINITY, t1 = -INFINITY;
        #pragma unroll
        for (int n = 0; n < 8; ++n) {
            t0 = fmaxf(t0, fmaxf(sv[4*n+0], sv[4*n+1]));
            t1 = fmaxf(t1, fmaxf(sv[4*n+2], sv[4*n+3]));
        }
        t0 = fmaxf(t0, __shfl_xor_sync(0xffffffffu, t0, 1));
        t0 = fmaxf(t0, __shfl_xor_sync(0xffffffffu, t0, 2));
        t1 = fmaxf(t1, __shfl_xor_sync(0xffffffffu, t1, 1));
        t1 = fmaxf(t1, __shfl_xor_sync(0xffffffffu, t1, 2));
        float M0n = fmaxf(M0, t0), M1n = fmaxf(M1, t1);
        float a0 = ex2f(M0 - M0n), a1 = ex2f(M1 - M1n);
        M0 = M0n; M1 = M1n;

        float l0 = 0.0f, l1 = 0.0f;
        #pragma unroll
        for (int n = 0; n < 8; ++n) {
            sv[4*n+0] = ex2f(sv[4*n+0] - M0n);
            sv[4*n+1] = ex2f(sv[4*n+1] - M0n);
            l0 += sv[4*n+0] + sv[4*n+1];
            sv[4*n+2] = ex2f(sv[4*n+2] - M1n);
            sv[4*n+3] = ex2f(sv[4*n+3] - M1n);
            l1 += sv[4*n+2] + sv[4*n+3];
        }
        l0 += __shfl_xor_sync(0xffffffffu, l0, 1);
        l0 += __shfl_xor_sync(0xffffffffu, l0, 2);
        l1 += __shfl_xor_sync(0xffffffffu, l1, 1);
        l1 += __shfl_xor_sync(0xffffffffu, l1, 2);
        L0 = L0 * a0 + l0;
        L1 = L1 * a1 + l1;
        #pragma unroll
        for (int n = 0; n < 16; ++n) {
            o[4*n+0] *= a0; o[4*n+1] *= a0;
            o[4*n+2] *= a1; o[4*n+3] *= a1;
        }

        // ---- P -> fp16 A-fragments (hi only) ----
        uint32_t ph[4][4];
        #pragma unroll
        for (int t = 0; t < 4; ++t)
            #pragma unroll
            for (int rix = 0; rix < 4; ++rix)
                ph[t][rix] = cvt2h(sv[8*t + 2*rix], sv[8*t + 2*rix + 1]);

        // ---- wait for V(kt) (and Khi(kt+1)) ----
        CP_WAIT0();
        __syncthreads();

        // ---- O += P V (single pass: Phi*Vhi) from B3 ----
        #pragma unroll
        for (int t = 0; t < 4; ++t) {                 // k16 tiles over BK=64
            #pragma unroll
            for (int g = 0; g < 8; ++g) {             // n16 groups over d=128
                uint32_t vh4[4];
                ldsm4t(vh4, voff + t * (16 * RSB) + g * 32);
                mma_f16(o + 8 * g,     ph[t], vh4);
                mma_f16(o + 8 * g + 4, ph[t], vh4 + 2);
            }
        }

        // ---- V dead: bring Klo(kt+1) into B3 ----
        __syncthreads();
        if (kt + 1 < nkt) copy17(sbase + SM_B3, &g_k[bh][kt + 1][TILE1], tid);
        CP_COMMIT();
    }

    // ---- epilogue: normalize, head_mask, store ----
    float li0 = hmv / L0, li1 = hmv / L1;
    float* o0 = out + ((size_t)bh * Sn + rg0) * Dh;
    float* o1 = o0 + 8 * Dh;
    #pragma unroll
    for (int n = 0; n < 16; ++n) {
        int c = 8 * n + c00;
        *reinterpret_cast<float2*>(o0 + c) = make_float2(o[4*n+0] * li0, o[4*n+1] * li0);
        *reinterpret_cast<float2*>(o1 + c) = make_float2(o[4*n+2] * li1, o[4*n+3] * li1);
    }
}

// ===================== launch =====================
extern "C" void kernel_launch(void* const* d_in, const int* in_sizes, int n_in,
                              void* d_out, int out_size)
{
    const float* q  = (const float*)d_in[0];
    const float* k  = (const float*)d_in[1];
    const float* v  = (const float*)d_in[2];
    const float* am = (const float*)d_in[3];
    const float* hm = (const float*)d_in[4];
    float* out = (float*)d_out;

    cudaFuncSetAttribute(fa_mma_kernel,
                         cudaFuncAttributeMaxDynamicSharedMemorySize, SM_TOTAL);

    prep_kernel<<<dim3(NTILES, NBH), 128>>>(k, v);
    dim3 grid(Sn / BQ, NBH);   // (32 q-tiles, 32 bh)
    fa_mma_kernel<<<grid, NT, SM_TOTAL>>>(q, am, hm, out);
}

// round 14
// speedup vs baseline: 1.0855x; 1.0855x over previous
#include <cuda_runtime.h>
#include <cuda_fp16.h>
#include <cstdint>
#include <math.h>

// ===================== problem constants =====================
constexpr int Bsz = 2;
constexpr int Hn  = 16;
constexpr int Sn  = 2048;
constexpr int Dh  = 128;

constexpr int BQ = 64;    // q rows per CTA (4 warps x 16 rows)
constexpr int BK = 128;   // k cols per iteration
constexpr int NT = 128;   // 4 warps
constexpr int NKT = Sn / BK;      // 16 k-tiles of 128 rows
constexpr int NBH = Bsz * Hn;     // 32

constexpr int RSB = 272;  // row stride in bytes (136 fp16) -> conflict-free ldmatrix
constexpr int TILE64  = 64  * RSB;    // 17408 B (Q hi or lo)
constexpr int TILE128 = 128 * RSB;    // 34816 B (K hi, K lo, V)

// smem: Q (hi+lo, 64 rows) | Khi (128 rows) | B3 = Klo during QK / V during PV | am
constexpr int SM_Q   = 0;
constexpr int SM_KHI = SM_Q + 2 * TILE64;   // 34816
constexpr int SM_B3  = SM_KHI + TILE128;    // 69632
constexpr int SM_AM  = SM_B3 + TILE128;     // 104448
constexpr int SM_TOTAL = SM_AM + BK * 4;    // 104960 B (x2 CTAs = 209.9KB/SM)

constexpr float LOG2E = 1.4426950408889634f;

// ===================== device scratch (converted tiles, padded layout) =====================
__device__ __align__(16) unsigned char g_k[NBH][NKT][2 * TILE128];  // hi at 0, lo at +TILE128
__device__ __align__(16) unsigned char g_v[NBH][NKT][TILE128];      // hi only

// ===================== helpers =====================
static __device__ __forceinline__ uint32_t smem_u32(const void* p) {
    uint32_t a;
    asm("{ .reg .u64 t; cvta.to.shared.u64 t, %1; cvt.u32.u64 %0, t; }" : "=r"(a) : "l"(p));
    return a;
}
static __device__ __forceinline__ void ldsm4(uint32_t* r, uint32_t a) {
    asm volatile("ldmatrix.sync.aligned.m8n8.x4.shared.b16 {%0,%1,%2,%3}, [%4];"
                 : "=r"(r[0]), "=r"(r[1]), "=r"(r[2]), "=r"(r[3]) : "r"(a));
}
static __device__ __forceinline__ void ldsm4t(uint32_t* r, uint32_t a) {
    asm volatile("ldmatrix.sync.aligned.m8n8.x4.trans.shared.b16 {%0,%1,%2,%3}, [%4];"
                 : "=r"(r[0]), "=r"(r[1]), "=r"(r[2]), "=r"(r[3]) : "r"(a));
}
static __device__ __forceinline__ void mma_f16(float* c, const uint32_t* a, const uint32_t* b) {
    asm volatile("mma.sync.aligned.m16n8k16.row.col.f32.f16.f16.f32 "
                 "{%0,%1,%2,%3},{%4,%5,%6,%7},{%8,%9},{%0,%1,%2,%3};"
                 : "+f"(c[0]), "+f"(c[1]), "+f"(c[2]), "+f"(c[3])
                 : "r"(a[0]), "r"(a[1]), "r"(a[2]), "r"(a[3]), "r"(b[0]), "r"(b[1]));
}
static __device__ __forceinline__ uint32_t cvt2h(float lo, float hi) {
    uint32_t r;
    asm("cvt.rn.f16x2.f32 %0, %1, %2;" : "=r"(r) : "f"(hi), "f"(lo));
    return r;
}
static __device__ __forceinline__ float2 h2f2(uint32_t u) {
    __half2 h = *reinterpret_cast<__half2*>(&u);
    return __half22float2(h);
}
static __device__ __forceinline__ float ex2f(float x) {
    float r;
    asm("ex2.approx.ftz.f32 %0, %1;" : "=f"(r) : "f"(x));
    return r;
}

#define CP16(s, g) \
    asm volatile("cp.async.cg.shared.global [%0], [%1], 16;" :: "r"(s), "l"(g) : "memory")
#define CP_COMMIT() asm volatile("cp.async.commit_group;" ::: "memory")
#define CP_WAIT0()  asm volatile("cp.async.wait_group 0;"  ::: "memory")

// async copy one 34816-B tile; exactly 17 chunks/thread
static __device__ __forceinline__ void copy34(uint32_t sdst,
                                              const unsigned char* gsrc, int tid) {
    unsigned long long ga = (unsigned long long)__cvta_generic_to_global((void*)gsrc);
    #pragma unroll
    for (int it = 0; it < 17; ++it) {
        int c = (it * NT + tid) * 16;
        CP16(sdst + c, ga + c);
    }
}

// fp32 -> fp16 hi/lo pair (padded layout); ROWS*16 chunks of 8 floats, 128 threads
template <int ROWS, bool SCALE>
static __device__ __forceinline__ void conv_pair(const float* __restrict__ g,
                                                 unsigned char* dst, int tid) {
    #pragma unroll
    for (int it = 0; it < (ROWS * 16) / 128; ++it) {
        int e = it * 128 + tid;
        int row = e >> 4, c8 = e & 15;
        const float4* src = reinterpret_cast<const float4*>(g) + 2 * e;
        float4 x = src[0], y = src[1];
        if (SCALE) {
            x.x *= LOG2E; x.y *= LOG2E; x.z *= LOG2E; x.w *= LOG2E;
            y.x *= LOG2E; y.y *= LOG2E; y.z *= LOG2E; y.w *= LOG2E;
        }
        uint32_t h0 = cvt2h(x.x, x.y), h1 = cvt2h(x.z, x.w);
        uint32_t h2 = cvt2h(y.x, y.y), h3 = cvt2h(y.z, y.w);
        float2 f0 = h2f2(h0), f1 = h2f2(h1), f2 = h2f2(h2), f3 = h2f2(h3);
        uint32_t l0 = cvt2h(x.x - f0.x, x.y - f0.y);
        uint32_t l1 = cvt2h(x.z - f1.x, x.w - f1.y);
        uint32_t l2 = cvt2h(y.x - f2.x, y.y - f2.y);
        uint32_t l3 = cvt2h(y.z - f3.x, y.w - f3.y);
        int off = row * RSB + c8 * 16;
        *reinterpret_cast<uint4*>(dst + off) = make_uint4(h0, h1, h2, h3);
        *reinterpret_cast<uint4*>(dst + ROWS * RSB + off) = make_uint4(l0, l1, l2, l3);
    }
}
static __device__ __forceinline__ void conv_hi128(const float* __restrict__ g,
                                                  unsigned char* dst, int tid) {
    #pragma unroll
    for (int it = 0; it < 16; ++it) {
        int e = it * 128 + tid;
        int row = e >> 4, c8 = e & 15;
        const float4* src = reinterpret_cast<const float4*>(g) + 2 * e;
        float4 x = src[0], y = src[1];
        uint32_t h0 = cvt2h(x.x, x.y), h1 = cvt2h(x.z, x.w);
        uint32_t h2 = cvt2h(y.x, y.y), h3 = cvt2h(y.z, y.w);
        int off = row * RSB + c8 * 16;
        *reinterpret_cast<uint4*>(dst + off) = make_uint4(h0, h1, h2, h3);
    }
}

// ===================== prepass: K (hi+lo), V (hi) in 128-row tiles =====================
__global__ __launch_bounds__(128)
void prep_kernel(const float* __restrict__ k, const float* __restrict__ v)
{
    const int kt = blockIdx.x, bh = blockIdx.y, tid = threadIdx.x;
    const size_t base = ((size_t)bh * Sn + (size_t)kt * BK) * Dh;
    conv_pair<128, false>(k + base, &g_k[bh][kt][0], tid);
    conv_hi128(v + base, &g_v[bh][kt][0], tid);
}

// ===================== main kernel =====================
__global__ __launch_bounds__(NT, 2)
void fa_mma_kernel(const float* __restrict__ q, const float* __restrict__ am,
                   const float* __restrict__ hm, float* __restrict__ out)
{
    extern __shared__ char smem[];
    const uint32_t sbase = smem_u32(smem);
    float* am_s = reinterpret_cast<float*>(smem + SM_AM);

    const int tid = threadIdx.x, wid = tid >> 5, lane = tid & 31;
    const int bh = blockIdx.y, b = bh >> 4, h = bh & 15;
    const int qt = (int)gridDim.x - 1 - (int)blockIdx.x;   // heavy tiles first
    const int q0 = qt * BQ;
    const int nkt = (qt >> 1) + 1;                         // 128-col tiles

    const float* amg = am + (size_t)b * Sn;
    const float  hmv = hm[h];

    // ---- prologue: issue K(0) cp.async, then convert Q (overlaps) ----
    copy34(sbase + SM_KHI, &g_k[bh][0][0], tid);
    copy34(sbase + SM_B3,  &g_k[bh][0][TILE128], tid);
    CP_COMMIT();
    conv_pair<64, true>(q + ((size_t)bh * Sn + q0) * Dh, (unsigned char*)smem + SM_Q, tid);

    // per-lane ldmatrix base addresses
    const int m0 = wid * 16;
    const uint32_t qoff = sbase + SM_Q + (m0 + (lane & 15)) * RSB + ((lane >> 4) & 1) * 16;
    const uint32_t koff = sbase + SM_KHI + ((lane & 7) + ((lane >> 4) & 1) * 8) * RSB + ((lane >> 3) & 1) * 16;
    const uint32_t voff = sbase + SM_B3 + ((lane & 7) + ((lane >> 3) & 1) * 8) * RSB + ((lane >> 4) & 1) * 16;
    constexpr int DKL = SM_B3 - SM_KHI;   // Klo offset relative to Khi

    float o[64];
    #pragma unroll
    for (int i = 0; i < 64; ++i) o[i] = 0.0f;
    float M0 = -INFINITY, M1 = -INFINITY, L0 = 0.0f, L1 = 0.0f;

    const int rg0 = q0 + m0 + (lane >> 2);   // global q row (upper)
    const int rg1 = rg0 + 8;
    const int c00 = 2 * (lane & 3);          // local col base within n8 tile

    for (int kt = 0; kt < nkt; ++kt) {
        // ---- wait for K(kt) (Klo in B3); Q STS ordered by this sync too ----
        CP_WAIT0();
        __syncthreads();
        am_s[tid] = amg[kt * BK + tid] * LOG2E;   // 128 threads, 128 cols

        // ---- S' = log2e * Q K^T (3-pass: Qhi*Khi + Qhi*Klo + Qlo*Khi), 16x128/warp ----
        float sv[64];
        #pragma unroll
        for (int i = 0; i < 64; ++i) sv[i] = 0.0f;
        #pragma unroll
        for (int t = 0; t < 8; ++t) {                 // k16 tiles over d=128
            uint32_t ah[4], al[4];
            ldsm4(ah, qoff + t * 32);
            ldsm4(al, qoff + TILE64 + t * 32);
            #pragma unroll
            for (int g = 0; g < 8; ++g) {             // n16 groups over 128 cols
                uint32_t bh4[4], bl4[4];
                ldsm4(bh4, koff + g * (16 * RSB) + t * 32);
                ldsm4(bl4, koff + DKL + g * (16 * RSB) + t * 32);
                mma_f16(sv + 8 * g,     ah, bh4);
                mma_f16(sv + 8 * g + 4, ah, bh4 + 2);
                mma_f16(sv + 8 * g,     ah, bl4);
                mma_f16(sv + 8 * g + 4, ah, bl4 + 2);
                mma_f16(sv + 8 * g,     al, bh4);
                mma_f16(sv + 8 * g + 4, al, bh4 + 2);
            }
        }

        // ---- K(kt) dead: bring V(kt) into B3, Khi(kt+1) into KHI ----
        __syncthreads();
        copy34(sbase + SM_B3, &g_v[bh][kt][0], tid);
        if (kt + 1 < nkt) copy34(sbase + SM_KHI, &g_k[bh][kt + 1][0], tid);
        CP_COMMIT();

        // ---- causal mask + additive attn_mask (log2 domain) ----
        float amr[32];
        #pragma unroll
        for (int n = 0; n < 16; ++n) {
            float2 a2 = *reinterpret_cast<const float2*>(&am_s[8 * n + c00]);
            amr[2 * n] = a2.x; amr[2 * n + 1] = a2.y;
        }
        if (kt == nkt - 1) {   // last tile: causal + over-allocation masking
            #pragma unroll
            for (int n = 0; n < 16; ++n) {
                int cg = kt * BK + 8 * n + c00;
                sv[4*n+0] = (cg     <= rg0) ? sv[4*n+0] + amr[2*n]   : -1e30f;
                sv[4*n+1] = (cg + 1 <= rg0) ? sv[4*n+1] + amr[2*n+1] : -1e30f;
                sv[4*n+2] = (cg     <= rg1) ? sv[4*n+2] + amr[2*n]   : -1e30f;
                sv[4*n+3] = (cg + 1 <= rg1) ? sv[4*n+3] + amr[2*n+1] : -1e30f;
            }
        } else {
            #pragma unroll
            for (int n = 0; n < 16; ++n) {
                sv[4*n+0] += amr[2*n];   sv[4*n+1] += amr[2*n+1];
                sv[4*n+2] += amr[2*n];   sv[4*n+3] += amr[2*n+1];
            }
        }

        // ---- online softmax in base-2 domain (overlaps V copy) ----
        float t0 = -INFINITY, t1 = -INFINITY;
        #pragma unroll
        for (int n = 0; n < 16; ++n) {
            t0 = fmaxf(t0, fmaxf(sv[4*n+0], sv[4*n+1]));
            t1 = fmaxf(t1, fmaxf(sv[4*n+2], sv[4*n+3]));
        }
        t0 = fmaxf(t0, __shfl_xor_sync(0xffffffffu, t0, 1));
        t0 = fmaxf(t0, __shfl_xor_sync(0xffffffffu, t0, 2));
        t1 = fmaxf(t1, __shfl_xor_sync(0xffffffffu, t1, 1));
        t1 = fmaxf(t1, __shfl_xor_sync(0xffffffffu, t1, 2));
        float M0n = fmaxf(M0, t0), M1n = fmaxf(M1, t1);
        float a0 = ex2f(M0 - M0n), a1 = ex2f(M1 - M1n);
        M0 = M0n; M1 = M1n;

        float l0 = 0.0f, l1 = 0.0f;
        #pragma unroll
        for (int n = 0; n < 16; ++n) {
            sv[4*n+0] = ex2f(sv[4*n+0] - M0n);
            sv[4*n+1] = ex2f(sv[4*n+1] - M0n);
            l0 += sv[4*n+0] + sv[4*n+1];
            sv[4*n+2] = ex2f(sv[4*n+2] - M1n);
            sv[4*n+3] = ex2f(sv[4*n+3] - M1n);
            l1 += sv[4*n+2] + sv[4*n+3];
        }
        l0 += __shfl_xor_sync(0xffffffffu, l0, 1);
        l0 += __shfl_xor_sync(0xffffffffu, l0, 2);
        l1 += __shfl_xor_sync(0xffffffffu, l1, 1);
        l1 += __shfl_xor_sync(0xffffffffu, l1, 2);
        L0 = L0 * a0 + l0;
        L1 = L1 * a1 + l1;
        #pragma unroll
        for (int n = 0; n < 16; ++n) {
            o[4*n+0] *= a0; o[4*n+1] *= a0;
            o[4*n+2] *= a1; o[4*n+3] *= a1;
        }

        // ---- P -> fp16 A-fragments (hi only); sv dies here ----
        uint32_t ph[8][4];
        #pragma unroll
        for (int t = 0; t < 8; ++t)
            #pragma unroll
            for (int rix = 0; rix < 4; ++rix)
                ph[t][rix] = cvt2h(sv[8*t + 2*rix], sv[8*t + 2*rix + 1]);

        // ---- wait for V(kt) (and Khi(kt+1)) ----
        CP_WAIT0();
        __syncthreads();

        // ---- O += P V (single pass: Phi*Vhi) from B3, 128 k-rows ----
        #pragma unroll
        for (int t = 0; t < 8; ++t) {                 // k16 tiles over BK=128
            #pragma unroll
            for (int g = 0; g < 8; ++g) {             // n16 groups over d=128
                uint32_t vh4[4];
                ldsm4t(vh4, voff + t * (16 * RSB) + g * 32);
                mma_f16(o + 8 * g,     ph[t], vh4);
                mma_f16(o + 8 * g + 4, ph[t], vh4 + 2);
            }
        }

        // ---- V dead: bring Klo(kt+1) into B3 ----
        __syncthreads();
        if (kt + 1 < nkt) copy34(sbase + SM_B3, &g_k[bh][kt + 1][TILE128], tid);
        CP_COMMIT();
    }

    // ---- epilogue: normalize, head_mask, store ----
    float li0 = hmv / L0, li1 = hmv / L1;
    float* o0 = out + ((size_t)bh * Sn + rg0) * Dh;
    float* o1 = o0 + 8 * Dh;
    #pragma unroll
    for (int n = 0; n < 16; ++n) {
        int c = 8 * n + c00;
        *reinterpret_cast<float2*>(o0 + c) = make_float2(o[4*n+0] * li0, o[4*n+1] * li0);
        *reinterpret_cast<float2*>(o1 + c) = make_float2(o[4*n+2] * li1, o[4*n+3] * li1);
    }
}

// ===================== launch =====================
extern "C" void kernel_launch(void* const* d_in, const int* in_sizes, int n_in,
                              void* d_out, int out_size)
{
    const float* q  = (const float*)d_in[0];
    const float* k  = (const float*)d_in[1];
    const float* v  = (const float*)d_in[2];
    const float* am = (const float*)d_in[3];
    const float* hm = (const float*)d_in[4];
    float* out = (float*)d_out;

    cudaFuncSetAttribute(fa_mma_kernel,
                         cudaFuncAttributeMaxDynamicSharedMemorySize, SM_TOTAL);

    prep_kernel<<<dim3(NKT, NBH), 128>>>(k, v);
    dim3 grid(Sn / BQ, NBH);   // (32 q-tiles, 32 bh)
    fa_mma_kernel<<<grid, NT, SM_TOTAL>>>(q, am, hm, out);
}

// round 15
// speedup vs baseline: 1.3178x; 1.2140x over previous
#include <cuda_runtime.h>
#include <cuda_fp16.h>
#include <cstdint>
#include <math.h>

// ===================== problem constants =====================
constexpr int Bsz = 2;
constexpr int Hn  = 16;
constexpr int Sn  = 2048;
constexpr int Dh  = 128;

constexpr int BQ = 64;    // q rows per CTA (4 warps x 16 rows)
constexpr int BK = 128;   // k cols per iteration
constexpr int NT = 128;   // 4 warps
constexpr int NKT = Sn / BK;      // 16 k-tiles of 128 rows
constexpr int NBH = Bsz * Hn;     // 32

constexpr int RSB = 272;  // full row stride (136 fp16) -> conflict-free ldmatrix
constexpr int RSL = 144;  // half-width lo-tile row stride (72 fp16) -> conflict-free
constexpr int TILE64  = 64  * RSB;    // 17408 B (Q hi)
constexpr int TILE128 = 128 * RSB;    // 34816 B (K hi, V)
constexpr int QLO_SZ  = 64  * RSL;    // 9216 B  (Q lo, d<64)
constexpr int KLO_SZ  = 128 * RSL;    // 18432 B (K lo, d<64)

// smem: Qhi | Qlo(half) | Khi | B3 (Klo-half during QK, V during PV) | am
constexpr int SM_QHI = 0;
constexpr int SM_QLO = SM_QHI + TILE64;    // 17408
constexpr int SM_KHI = SM_QLO + QLO_SZ;    // 26624
constexpr int SM_B3  = SM_KHI + TILE128;   // 61440
constexpr int SM_AM  = SM_B3 + TILE128;    // 96256
constexpr int SM_TOTAL = SM_AM + BK * 4;   // 96768 B (x2 CTAs = 193.5KB/SM)

constexpr float LOG2E = 1.4426950408889634f;

// ===================== device scratch (converted tiles) =====================
__device__ __align__(16) unsigned char g_khi[NBH][NKT][TILE128];
__device__ __align__(16) unsigned char g_klo[NBH][NKT][KLO_SZ];   // d<64 only
__device__ __align__(16) unsigned char g_v  [NBH][NKT][TILE128];  // hi only

// ===================== helpers =====================
static __device__ __forceinline__ uint32_t smem_u32(const void* p) {
    uint32_t a;
    asm("{ .reg .u64 t; cvta.to.shared.u64 t, %1; cvt.u32.u64 %0, t; }" : "=r"(a) : "l"(p));
    return a;
}
static __device__ __forceinline__ void ldsm4(uint32_t* r, uint32_t a) {
    asm volatile("ldmatrix.sync.aligned.m8n8.x4.shared.b16 {%0,%1,%2,%3}, [%4];"
                 : "=r"(r[0]), "=r"(r[1]), "=r"(r[2]), "=r"(r[3]) : "r"(a));
}
static __device__ __forceinline__ void ldsm4t(uint32_t* r, uint32_t a) {
    asm volatile("ldmatrix.sync.aligned.m8n8.x4.trans.shared.b16 {%0,%1,%2,%3}, [%4];"
                 : "=r"(r[0]), "=r"(r[1]), "=r"(r[2]), "=r"(r[3]) : "r"(a));
}
static __device__ __forceinline__ void mma_f16(float* c, const uint32_t* a, const uint32_t* b) {
    asm volatile("mma.sync.aligned.m16n8k16.row.col.f32.f16.f16.f32 "
                 "{%0,%1,%2,%3},{%4,%5,%6,%7},{%8,%9},{%0,%1,%2,%3};"
                 : "+f"(c[0]), "+f"(c[1]), "+f"(c[2]), "+f"(c[3])
                 : "r"(a[0]), "r"(a[1]), "r"(a[2]), "r"(a[3]), "r"(b[0]), "r"(b[1]));
}
static __device__ __forceinline__ uint32_t cvt2h(float lo, float hi) {
    uint32_t r;
    asm("cvt.rn.f16x2.f32 %0, %1, %2;" : "=r"(r) : "f"(hi), "f"(lo));
    return r;
}
static __device__ __forceinline__ float2 h2f2(uint32_t u) {
    __half2 h = *reinterpret_cast<__half2*>(&u);
    return __half22float2(h);
}
static __device__ __forceinline__ float ex2f(float x) {
    float r;
    asm("ex2.approx.ftz.f32 %0, %1;" : "=f"(r) : "f"(x));
    return r;
}

#define CP16(s, g) \
    asm volatile("cp.async.cg.shared.global [%0], [%1], 16;" :: "r"(s), "l"(g) : "memory")
#define CP_COMMIT() asm volatile("cp.async.commit_group;" ::: "memory")
#define CP_WAIT0()  asm volatile("cp.async.wait_group 0;"  ::: "memory")

// async copy 34816-B tile; 17 chunks/thread
static __device__ __forceinline__ void copy34(uint32_t sdst,
                                              const unsigned char* gsrc, int tid) {
    unsigned long long ga = (unsigned long long)__cvta_generic_to_global((void*)gsrc);
    #pragma unroll
    for (int it = 0; it < 17; ++it) {
        int c = (it * NT + tid) * 16;
        CP16(sdst + c, ga + c);
    }
}
// async copy 18432-B tile; exactly 9 chunks/thread
static __device__ __forceinline__ void copy18(uint32_t sdst,
                                              const unsigned char* gsrc, int tid) {
    unsigned long long ga = (unsigned long long)__cvta_generic_to_global((void*)gsrc);
    #pragma unroll
    for (int it = 0; it < 9; ++it) {
        int c = (it * NT + tid) * 16;
        CP16(sdst + c, ga + c);
    }
}

// fp32 -> fp16: hi full (RSB stride) + lo for d<64 (RSL stride). ROWS in {64,128}.
template <int ROWS, bool SCALE>
static __device__ __forceinline__ void conv_halfcomp(const float* __restrict__ g,
                                                     unsigned char* hidst,
                                                     unsigned char* lodst, int tid) {
    #pragma unroll
    for (int it = 0; it < (ROWS * 16) / 128; ++it) {
        int e = it * 128 + tid;
        int row = e >> 4, c8 = e & 15;
        const float4* src = reinterpret_cast<const float4*>(g) + 2 * e;
        float4 x = src[0], y = src[1];
        if (SCALE) {
            x.x *= LOG2E; x.y *= LOG2E; x.z *= LOG2E; x.w *= LOG2E;
            y.x *= LOG2E; y.y *= LOG2E; y.z *= LOG2E; y.w *= LOG2E;
        }
        uint32_t h0 = cvt2h(x.x, x.y), h1 = cvt2h(x.z, x.w);
        uint32_t h2 = cvt2h(y.x, y.y), h3 = cvt2h(y.z, y.w);
        *reinterpret_cast<uint4*>(hidst + row * RSB + c8 * 16) = make_uint4(h0, h1, h2, h3);
        if (c8 < 8) {   // d < 64: write compensation
            float2 f0 = h2f2(h0), f1 = h2f2(h1), f2 = h2f2(h2), f3 = h2f2(h3);
            uint32_t l0 = cvt2h(x.x - f0.x, x.y - f0.y);
            uint32_t l1 = cvt2h(x.z - f1.x, x.w - f1.y);
            uint32_t l2 = cvt2h(y.x - f2.x, y.y - f2.y);
            uint32_t l3 = cvt2h(y.z - f3.x, y.w - f3.y);
            *reinterpret_cast<uint4*>(lodst + row * RSL + c8 * 16) = make_uint4(l0, l1, l2, l3);
        }
    }
}
static __device__ __forceinline__ void conv_hi128(const float* __restrict__ g,
                                                  unsigned char* dst, int tid) {
    #pragma unroll
    for (int it = 0; it < 16; ++it) {
        int e = it * 128 + tid;
        int row = e >> 4, c8 = e & 15;
        const float4* src = reinterpret_cast<const float4*>(g) + 2 * e;
        float4 x = src[0], y = src[1];
        uint32_t h0 = cvt2h(x.x, x.y), h1 = cvt2h(x.z, x.w);
        uint32_t h2 = cvt2h(y.x, y.y), h3 = cvt2h(y.z, y.w);
        *reinterpret_cast<uint4*>(dst + row * RSB + c8 * 16) = make_uint4(h0, h1, h2, h3);
    }
}

// ===================== prepass =====================
__global__ __launch_bounds__(128)
void prep_kernel(const float* __restrict__ k, const float* __restrict__ v)
{
    const int kt = blockIdx.x, bh = blockIdx.y, tid = threadIdx.x;
    const size_t base = ((size_t)bh * Sn + (size_t)kt * BK) * Dh;
    conv_halfcomp<128, false>(k + base, &g_khi[bh][kt][0], &g_klo[bh][kt][0], tid);
    conv_hi128(v + base, &g_v[bh][kt][0], tid);
}

// ===================== main kernel =====================
__global__ __launch_bounds__(NT, 2)
void fa_mma_kernel(const float* __restrict__ q, const float* __restrict__ am,
                   const float* __restrict__ hm, float* __restrict__ out)
{
    extern __shared__ char smem[];
    const uint32_t sbase = smem_u32(smem);
    float* am_s = reinterpret_cast<float*>(smem + SM_AM);

    const int tid = threadIdx.x, wid = tid >> 5, lane = tid & 31;
    const int bh = blockIdx.y, b = bh >> 4, h = bh & 15;
    const int qt = (int)gridDim.x - 1 - (int)blockIdx.x;   // heavy tiles first
    const int q0 = qt * BQ;
    const int nkt = (qt >> 1) + 1;                         // 128-col tiles

    const float* amg = am + (size_t)b * Sn;
    const float  hmv = hm[h];

    // ---- prologue: issue Khi(0)+Klo(0) cp.async, then convert Q (overlaps) ----
    copy34(sbase + SM_KHI, &g_khi[bh][0][0], tid);
    copy18(sbase + SM_B3,  &g_klo[bh][0][0], tid);
    CP_COMMIT();
    conv_halfcomp<64, true>(q + ((size_t)bh * Sn + q0) * Dh,
                            (unsigned char*)smem + SM_QHI,
                            (unsigned char*)smem + SM_QLO, tid);

    // per-lane ldmatrix base addresses
    const int m0 = wid * 16;
    const uint32_t qoff  = sbase + SM_QHI + (m0 + (lane & 15)) * RSB + ((lane >> 4) & 1) * 16;
    const uint32_t qloff = sbase + SM_QLO + (m0 + (lane & 15)) * RSL + ((lane >> 4) & 1) * 16;
    const uint32_t koff  = sbase + SM_KHI + ((lane & 7) + ((lane >> 4) & 1) * 8) * RSB + ((lane >> 3) & 1) * 16;
    const uint32_t kloff = sbase + SM_B3  + ((lane & 7) + ((lane >> 4) & 1) * 8) * RSL + ((lane >> 3) & 1) * 16;
    const uint32_t voff  = sbase + SM_B3  + ((lane & 7) + ((lane >> 3) & 1) * 8) * RSB + ((lane >> 4) & 1) * 16;

    float o[64];
    #pragma unroll
    for (int i = 0; i < 64; ++i) o[i] = 0.0f;
    float M0 = -INFINITY, M1 = -INFINITY, L0 = 0.0f, L1 = 0.0f;

    const int rg0 = q0 + m0 + (lane >> 2);   // global q row (upper)
    const int rg1 = rg0 + 8;
    const int c00 = 2 * (lane & 3);          // local col base within n8 tile

    for (int kt = 0; kt < nkt; ++kt) {
        // ---- wait for Khi(kt) + Klo(kt); Q STS also ordered by the sync ----
        CP_WAIT0();
        __syncthreads();
        am_s[tid] = amg[kt * BK + tid] * LOG2E;   // consumed after post-QK sync

        // ---- S' = log2e * Q K^T: hi*hi over full d; corrections only d<64 ----
        float sv[64];
        #pragma unroll
        for (int i = 0; i < 64; ++i) sv[i] = 0.0f;
        #pragma unroll
        for (int t = 0; t < 8; ++t) {                 // k16 tiles over d=128
            uint32_t ah[4], al[4];
            ldsm4(ah, qoff + t * 32);
            if (t < 4) ldsm4(al, qloff + t * 32);
            #pragma unroll
            for (int g = 0; g < 8; ++g) {             // n16 groups over 128 cols
                uint32_t bh4[4];
                ldsm4(bh4, koff + g * (16 * RSB) + t * 32);
                mma_f16(sv + 8 * g,     ah, bh4);
                mma_f16(sv + 8 * g + 4, ah, bh4 + 2);
                if (t < 4) {
                    uint32_t bl4[4];
                    ldsm4(bl4, kloff + g * (16 * RSL) + t * 32);
                    mma_f16(sv + 8 * g,     ah, bl4);
                    mma_f16(sv + 8 * g + 4, ah, bl4 + 2);
                    mma_f16(sv + 8 * g,     al, bh4);
                    mma_f16(sv + 8 * g + 4, al, bh4 + 2);
                }
            }
        }

        // ---- K(kt) dead: bring V(kt) into B3, Khi(kt+1) into KHI ----
        __syncthreads();
        copy34(sbase + SM_B3, &g_v[bh][kt][0], tid);
        if (kt + 1 < nkt) copy34(sbase + SM_KHI, &g_khi[bh][kt + 1][0], tid);
        CP_COMMIT();

        // ---- causal mask + additive attn_mask (log2 domain) ----
        float amr[32];
        #pragma unroll
        for (int n = 0; n < 16; ++n) {
            float2 a2 = *reinterpret_cast<const float2*>(&am_s[8 * n + c00]);
            amr[2 * n] = a2.x; amr[2 * n + 1] = a2.y;
        }
        if (kt == nkt - 1) {   // last tile: causal + over-allocation masking
            #pragma unroll
            for (int n = 0; n < 16; ++n) {
                int cg = kt * BK + 8 * n + c00;
                sv[4*n+0] = (cg     <= rg0) ? sv[4*n+0] + amr[2*n]   : -1e30f;
                sv[4*n+1] = (cg + 1 <= rg0) ? sv[4*n+1] + amr[2*n+1] : -1e30f;
                sv[4*n+2] = (cg     <= rg1) ? sv[4*n+2] + amr[2*n]   : -1e30f;
                sv[4*n+3] = (cg + 1 <= rg1) ? sv[4*n+3] + amr[2*n+1] : -1e30f;
            }
        } else {
            #pragma unroll
            for (int n = 0; n < 16; ++n) {
                sv[4*n+0] += amr[2*n];   sv[4*n+1] += amr[2*n+1];
                sv[4*n+2] += amr[2*n];   sv[4*n+3] += amr[2*n+1];
            }
        }

        // ---- online softmax in base-2 domain (overlaps V copy) ----
        float t0 = -INFINITY, t1 = -INFINITY;
        #pragma unroll
        for (int n = 0; n < 16; ++n) {
            t0 = fmaxf(t0, fmaxf(sv[4*n+0], sv[4*n+1]));
            t1 = fmaxf(t1, fmaxf(sv[4*n+2], sv[4*n+3]));
        }
        t0 = fmaxf(t0, __shfl_xor_sync(0xffffffffu, t0, 1));
        t0 = fmaxf(t0, __shfl_xor_sync(0xffffffffu, t0, 2));
        t1 = fmaxf(t1, __shfl_xor_sync(0xffffffffu, t1, 1));
        t1 = fmaxf(t1, __shfl_xor_sync(0xffffffffu, t1, 2));
        float M0n = fmaxf(M0, t0), M1n = fmaxf(M1, t1);
        float a0 = ex2f(M0 - M0n), a1 = ex2f(M1 - M1n);
        M0 = M0n; M1 = M1n;

        float l0 = 0.0f, l1 = 0.0f;
        #pragma unroll
        for (int n = 0; n < 16; ++n) {
            sv[4*n+0] = ex2f(sv[4*n+0] - M0n);
            sv[4*n+1] = ex2f(sv[4*n+1] - M0n);
            l0 += sv[4*n+0] + sv[4*n+1];
            sv[4*n+2] = ex2f(sv[4*n+2] - M1n);
            sv[4*n+3] = ex2f(sv[4*n+3] - M1n);
            l1 += sv[4*n+2] + sv[4*n+3];
        }
        l0 += __shfl_xor_sync(0xffffffffu, l0, 1);
        l0 += __shfl_xor_sync(0xffffffffu, l0, 2);
        l1 += __shfl_xor_sync(0xffffffffu, l1, 1);
        l1 += __shfl_xor_sync(0xffffffffu, l1, 2);
        L0 = L0 * a0 + l0;
        L1 = L1 * a1 + l1;
        #pragma unroll
        for (int n = 0; n < 16; ++n) {
            o[4*n+0] *= a0; o[4*n+1] *= a0;
            o[4*n+2] *= a1; o[4*n+3] *= a1;
        }

        // ---- P -> fp16 A-fragments (hi only); sv dies here ----
        uint32_t ph[8][4];
        #pragma unroll
        for (int t = 0; t < 8; ++t)
            #pragma unroll
            for (int rix = 0; rix < 4; ++rix)
                ph[t][rix] = cvt2h(sv[8*t + 2*rix], sv[8*t + 2*rix + 1]);

        // ---- wait for V(kt) (and Khi(kt+1)) ----
        CP_WAIT0();
        __syncthreads();

        // ---- O += P V (single pass: Phi*Vhi) from B3, 128 k-rows ----
        #pragma unroll
        for (int t = 0; t < 8; ++t) {                 // k16 tiles over BK=128
            #pragma unroll
            for (int g = 0; g < 8; ++g) {             // n16 groups over d=128
                uint32_t vh4[4];
                ldsm4t(vh4, voff + t * (16 * RSB) + g * 32);
                mma_f16(o + 8 * g,     ph[t], vh4);
                mma_f16(o + 8 * g + 4, ph[t], vh4 + 2);
            }
        }

        // ---- V dead: bring Klo(kt+1) into B3 ----
        __syncthreads();
        if (kt + 1 < nkt) copy18(sbase + SM_B3, &g_klo[bh][kt + 1][0], tid);
        CP_COMMIT();
    }

    // ---- epilogue: normalize, head_mask, store ----
    float li0 = hmv / L0, li1 = hmv / L1;
    float* o0 = out + ((size_t)bh * Sn + rg0) * Dh;
    float* o1 = o0 + 8 * Dh;
    #pragma unroll
    for (int n = 0; n < 16; ++n) {
        int c = 8 * n + c00;
        *reinterpret_cast<float2*>(o0 + c) = make_float2(o[4*n+0] * li0, o[4*n+1] * li0);
        *reinterpret_cast<float2*>(o1 + c) = make_float2(o[4*n+2] * li1, o[4*n+3] * li1);
    }
}

// ===================== launch =====================
extern "C" void kernel_launch(void* const* d_in, const int* in_sizes, int n_in,
                              void* d_out, int out_size)
{
    const float* q  = (const float*)d_in[0];
    const float* k  = (const float*)d_in[1];
    const float* v  = (const float*)d_in[2];
    const float* am = (const float*)d_in[3];
    const float* hm = (const float*)d_in[4];
    float* out = (float*)d_out;

    cudaFuncSetAttribute(fa_mma_kernel,
                         cudaFuncAttributeMaxDynamicSharedMemorySize, SM_TOTAL);

    prep_kernel<<<dim3(NKT, NBH), 128>>>(k, v);
    dim3 grid(Sn / BQ, NBH);   // (32 q-tiles, 32 bh)
    fa_mma_kernel<<<grid, NT, SM_TOTAL>>>(q, am, hm, out);
}

// round 16
// speedup vs baseline: 1.3717x; 1.0409x over previous
#include <cuda_runtime.h>
#include <cuda_fp16.h>
#include <cstdint>
#include <math.h>

// ===================== problem constants =====================
constexpr int Bsz = 2;
constexpr int Hn  = 16;
constexpr int Sn  = 2048;
constexpr int Dh  = 128;

constexpr int BQ = 64;    // q rows per CTA (4 warps x 16 rows)
constexpr int BK = 128;   // k cols per iteration
constexpr int NT = 128;   // 4 warps
constexpr int NKT = Sn / BK;      // 16 k-tiles of 128 rows
constexpr int NBH = Bsz * Hn;     // 32

constexpr int RSB = 272;  // row stride in bytes (136 fp16) -> conflict-free ldmatrix
constexpr int TILE64  = 64  * RSB;    // 17408 B (Q hi / Q lo)
constexpr int TILE128 = 128 * RSB;    // 34816 B (K hi, V hi)

// smem: Qhi | Qlo | Khi | V | am
constexpr int SM_QHI = 0;
constexpr int SM_QLO = SM_QHI + TILE64;    // 17408
constexpr int SM_KHI = SM_QLO + TILE64;    // 34816
constexpr int SM_V   = SM_KHI + TILE128;   // 69632
constexpr int SM_AM  = SM_V + TILE128;     // 104448
constexpr int SM_TOTAL = SM_AM + BK * 4;   // 104960 B (x2 CTAs = 209.9KB/SM)

constexpr float LOG2E = 1.4426950408889634f;

// ===================== device scratch (converted tiles, hi only) =====================
__device__ __align__(16) unsigned char g_khi[NBH][NKT][TILE128];
__device__ __align__(16) unsigned char g_v  [NBH][NKT][TILE128];

// ===================== helpers =====================
static __device__ __forceinline__ uint32_t smem_u32(const void* p) {
    uint32_t a;
    asm("{ .reg .u64 t; cvta.to.shared.u64 t, %1; cvt.u32.u64 %0, t; }" : "=r"(a) : "l"(p));
    return a;
}
static __device__ __forceinline__ void ldsm4(uint32_t* r, uint32_t a) {
    asm volatile("ldmatrix.sync.aligned.m8n8.x4.shared.b16 {%0,%1,%2,%3}, [%4];"
                 : "=r"(r[0]), "=r"(r[1]), "=r"(r[2]), "=r"(r[3]) : "r"(a));
}
static __device__ __forceinline__ void ldsm4t(uint32_t* r, uint32_t a) {
    asm volatile("ldmatrix.sync.aligned.m8n8.x4.trans.shared.b16 {%0,%1,%2,%3}, [%4];"
                 : "=r"(r[0]), "=r"(r[1]), "=r"(r[2]), "=r"(r[3]) : "r"(a));
}
static __device__ __forceinline__ void mma_f16(float* c, const uint32_t* a, const uint32_t* b) {
    asm volatile("mma.sync.aligned.m16n8k16.row.col.f32.f16.f16.f32 "
                 "{%0,%1,%2,%3},{%4,%5,%6,%7},{%8,%9},{%0,%1,%2,%3};"
                 : "+f"(c[0]), "+f"(c[1]), "+f"(c[2]), "+f"(c[3])
                 : "r"(a[0]), "r"(a[1]), "r"(a[2]), "r"(a[3]), "r"(b[0]), "r"(b[1]));
}
static __device__ __forceinline__ uint32_t cvt2h(float lo, float hi) {
    uint32_t r;
    asm("cvt.rn.f16x2.f32 %0, %1, %2;" : "=r"(r) : "f"(hi), "f"(lo));
    return r;
}
static __device__ __forceinline__ float2 h2f2(uint32_t u) {
    __half2 h = *reinterpret_cast<__half2*>(&u);
    return __half22float2(h);
}
static __device__ __forceinline__ float ex2f(float x) {
    float r;
    asm("ex2.approx.ftz.f32 %0, %1;" : "=f"(r) : "f"(x));
    return r;
}

#define CP16(s, g) \
    asm volatile("cp.async.cg.shared.global [%0], [%1], 16;" :: "r"(s), "l"(g) : "memory")
#define CP_COMMIT() asm volatile("cp.async.commit_group;" ::: "memory")
#define CP_WAIT(n)  asm volatile("cp.async.wait_group %0;" :: "n"(n) : "memory")

// async copy 34816-B tile; 17 chunks/thread
static __device__ __forceinline__ void copy34(uint32_t sdst,
                                              const unsigned char* gsrc, int tid) {
    unsigned long long ga = (unsigned long long)__cvta_generic_to_global((void*)gsrc);
    #pragma unroll
    for (int it = 0; it < 17; ++it) {
        int c = (it * NT + tid) * 16;
        CP16(sdst + c, ga + c);
    }
}

// fp32 -> fp16 hi/lo pair (full width, RSB stride); 64 rows
static __device__ __forceinline__ void conv_q(const float* __restrict__ g,
                                              unsigned char* hidst,
                                              unsigned char* lodst, int tid) {
    #pragma unroll
    for (int it = 0; it < 8; ++it) {
        int e = it * 128 + tid;                // 1024 chunks of 8 floats
        int row = e >> 4, c8 = e & 15;
        const float4* src = reinterpret_cast<const float4*>(g) + 2 * e;
        float4 x = src[0], y = src[1];
        x.x *= LOG2E; x.y *= LOG2E; x.z *= LOG2E; x.w *= LOG2E;
        y.x *= LOG2E; y.y *= LOG2E; y.z *= LOG2E; y.w *= LOG2E;
        uint32_t h0 = cvt2h(x.x, x.y), h1 = cvt2h(x.z, x.w);
        uint32_t h2 = cvt2h(y.x, y.y), h3 = cvt2h(y.z, y.w);
        float2 f0 = h2f2(h0), f1 = h2f2(h1), f2 = h2f2(h2), f3 = h2f2(h3);
        uint32_t l0 = cvt2h(x.x - f0.x, x.y - f0.y);
        uint32_t l1 = cvt2h(x.z - f1.x, x.w - f1.y);
        uint32_t l2 = cvt2h(y.x - f2.x, y.y - f2.y);
        uint32_t l3 = cvt2h(y.z - f3.x, y.w - f3.y);
        int off = row * RSB + c8 * 16;
        *reinterpret_cast<uint4*>(hidst + off) = make_uint4(h0, h1, h2, h3);
        *reinterpret_cast<uint4*>(lodst + off) = make_uint4(l0, l1, l2, l3);
    }
}
static __device__ __forceinline__ void conv_hi128(const float* __restrict__ g,
                                                  unsigned char* dst, int tid) {
    #pragma unroll
    for (int it = 0; it < 16; ++it) {
        int e = it * 128 + tid;
        int row = e >> 4, c8 = e & 15;
        const float4* src = reinterpret_cast<const float4*>(g) + 2 * e;
        float4 x = src[0], y = src[1];
        uint32_t h0 = cvt2h(x.x, x.y), h1 = cvt2h(x.z, x.w);
        uint32_t h2 = cvt2h(y.x, y.y), h3 = cvt2h(y.z, y.w);
        *reinterpret_cast<uint4*>(dst + row * RSB + c8 * 16) = make_uint4(h0, h1, h2, h3);
    }
}

// ===================== prepass: K hi, V hi =====================
__global__ __launch_bounds__(128)
void prep_kernel(const float* __restrict__ k, const float* __restrict__ v)
{
    const int kt = blockIdx.x, bh = blockIdx.y, tid = threadIdx.x;
    const size_t base = ((size_t)bh * Sn + (size_t)kt * BK) * Dh;
    conv_hi128(k + base, &g_khi[bh][kt][0], tid);
    conv_hi128(v + base, &g_v[bh][kt][0], tid);
}

// ===================== main kernel =====================
__global__ __launch_bounds__(NT, 2)
void fa_mma_kernel(const float* __restrict__ q, const float* __restrict__ am,
                   const float* __restrict__ hm, float* __restrict__ out)
{
    extern __shared__ char smem[];
    const uint32_t sbase = smem_u32(smem);
    float* am_s = reinterpret_cast<float*>(smem + SM_AM);

    const int tid = threadIdx.x, wid = tid >> 5, lane = tid & 31;
    const int bh = blockIdx.y, b = bh >> 4, h = bh & 15;
    const int qt = (int)gridDim.x - 1 - (int)blockIdx.x;   // heavy tiles first
    const int q0 = qt * BQ;
    const int nkt = (qt >> 1) + 1;                         // 128-col tiles

    const float* amg = am + (size_t)b * Sn;
    const float  hmv = hm[h];

    // ---- prologue: Khi(0) [group], V(0) [group], then convert Q (overlaps) ----
    copy34(sbase + SM_KHI, &g_khi[bh][0][0], tid);
    CP_COMMIT();
    copy34(sbase + SM_V, &g_v[bh][0][0], tid);
    CP_COMMIT();
    conv_q(q + ((size_t)bh * Sn + q0) * Dh,
           (unsigned char*)smem + SM_QHI, (unsigned char*)smem + SM_QLO, tid);

    // per-lane ldmatrix base addresses
    const int m0 = wid * 16;
    const uint32_t qoff  = sbase + SM_QHI + (m0 + (lane & 15)) * RSB + ((lane >> 4) & 1) * 16;
    const uint32_t koff  = sbase + SM_KHI + ((lane & 7) + ((lane >> 4) & 1) * 8) * RSB + ((lane >> 3) & 1) * 16;
    const uint32_t voff  = sbase + SM_V   + ((lane & 7) + ((lane >> 3) & 1) * 8) * RSB + ((lane >> 4) & 1) * 16;
    constexpr int DQL = SM_QLO - SM_QHI;

    float o[64];
    #pragma unroll
    for (int i = 0; i < 64; ++i) o[i] = 0.0f;
    float M0 = -INFINITY, M1 = -INFINITY, L0 = 0.0f, L1 = 0.0f;

    const int rg0 = q0 + m0 + (lane >> 2);   // global q row (upper)
    const int rg1 = rg0 + 8;
    const int c00 = 2 * (lane & 3);          // local col base within n8 tile

    for (int kt = 0; kt < nkt; ++kt) {
        // ---- wait for Khi(kt) (V(kt) may still be in flight) ----
        CP_WAIT(1);
        __syncthreads();
        am_s[tid] = amg[kt * BK + tid] * LOG2E;   // consumed after post-QK sync

        // ---- S' = log2e * Q K^T (2-pass: Qhi*Khi + Qlo*Khi), 16x128/warp ----
        float sv[64];
        #pragma unroll
        for (int i = 0; i < 64; ++i) sv[i] = 0.0f;
        #pragma unroll
        for (int t = 0; t < 8; ++t) {                 // k16 tiles over d=128
            uint32_t ah[4], al[4];
            ldsm4(ah, qoff + t * 32);
            ldsm4(al, qoff + DQL + t * 32);
            #pragma unroll
            for (int g = 0; g < 8; ++g) {             // n16 groups over 128 cols
                uint32_t bh4[4];
                ldsm4(bh4, koff + g * (16 * RSB) + t * 32);
                mma_f16(sv + 8 * g,     ah, bh4);
                mma_f16(sv + 8 * g + 4, ah, bh4 + 2);
                mma_f16(sv + 8 * g,     al, bh4);
                mma_f16(sv + 8 * g + 4, al, bh4 + 2);
            }
        }

        // ---- K(kt) dead -> prefetch Khi(kt+1); covered by softmax+PV ----
        __syncthreads();
        if (kt + 1 < nkt) copy34(sbase + SM_KHI, &g_khi[bh][kt + 1][0], tid);
        CP_COMMIT();                                   // unconditional: group counts stay aligned

        // ---- causal mask + additive attn_mask (log2 domain) ----
        float amr[32];
        #pragma unroll
        for (int n = 0; n < 16; ++n) {
            float2 a2 = *reinterpret_cast<const float2*>(&am_s[8 * n + c00]);
            amr[2 * n] = a2.x; amr[2 * n + 1] = a2.y;
        }
        if (kt == nkt - 1) {   // last tile: causal + over-allocation masking
            #pragma unroll
            for (int n = 0; n < 16; ++n) {
                int cg = kt * BK + 8 * n + c00;
                sv[4*n+0] = (cg     <= rg0) ? sv[4*n+0] + amr[2*n]   : -1e30f;
                sv[4*n+1] = (cg + 1 <= rg0) ? sv[4*n+1] + amr[2*n+1] : -1e30f;
                sv[4*n+2] = (cg     <= rg1) ? sv[4*n+2] + amr[2*n]   : -1e30f;
                sv[4*n+3] = (cg + 1 <= rg1) ? sv[4*n+3] + amr[2*n+1] : -1e30f;
            }
        } else {
            #pragma unroll
            for (int n = 0; n < 16; ++n) {
                sv[4*n+0] += amr[2*n];   sv[4*n+1] += amr[2*n+1];
                sv[4*n+2] += amr[2*n];   sv[4*n+3] += amr[2*n+1];
            }
        }

        // ---- online softmax in base-2 domain ----
        float t0 = -INFINITY, t1 = -INFINITY;
        #pragma unroll
        for (int n = 0; n < 16; ++n) {
            t0 = fmaxf(t0, fmaxf(sv[4*n+0], sv[4*n+1]));
            t1 = fmaxf(t1, fmaxf(sv[4*n+2], sv[4*n+3]));
        }
        t0 = fmaxf(t0, __shfl_xor_sync(0xffffffffu, t0, 1));
        t0 = fmaxf(t0, __shfl_xor_sync(0xffffffffu, t0, 2));
        t1 = fmaxf(t1, __shfl_xor_sync(0xffffffffu, t1, 1));
        t1 = fmaxf(t1, __shfl_xor_sync(0xffffffffu, t1, 2));
        float M0n = fmaxf(M0, t0), M1n = fmaxf(M1, t1);
        float a0 = ex2f(M0 - M0n), a1 = ex2f(M1 - M1n);
        M0 = M0n; M1 = M1n;

        float l0 = 0.0f, l1 = 0.0f;
        #pragma unroll
        for (int n = 0; n < 16; ++n) {
            sv[4*n+0] = ex2f(sv[4*n+0] - M0n);
            sv[4*n+1] = ex2f(sv[4*n+1] - M0n);
            l0 += sv[4*n+0] + sv[4*n+1];
            sv[4*n+2] = ex2f(sv[4*n+2] - M1n);
            sv[4*n+3] = ex2f(sv[4*n+3] - M1n);
            l1 += sv[4*n+2] + sv[4*n+3];
        }
        l0 += __shfl_xor_sync(0xffffffffu, l0, 1);
        l0 += __shfl_xor_sync(0xffffffffu, l0, 2);
        l1 += __shfl_xor_sync(0xffffffffu, l1, 1);
        l1 += __shfl_xor_sync(0xffffffffu, l1, 2);
        L0 = L0 * a0 + l0;
        L1 = L1 * a1 + l1;
        #pragma unroll
        for (int n = 0; n < 16; ++n) {
            o[4*n+0] *= a0; o[4*n+1] *= a0;
            o[4*n+2] *= a1; o[4*n+3] *= a1;
        }

        // ---- P -> fp16 A-fragments (hi only); sv dies here ----
        uint32_t ph[8][4];
        #pragma unroll
        for (int t = 0; t < 8; ++t)
            #pragma unroll
            for (int rix = 0; rix < 4; ++rix)
                ph[t][rix] = cvt2h(sv[8*t + 2*rix], sv[8*t + 2*rix + 1]);

        // ---- wait for V(kt) (Khi(kt+1) may still be in flight) ----
        CP_WAIT(1);
        __syncthreads();

        // ---- O += P V (single pass: Phi*Vhi), 128 k-rows ----
        #pragma unroll
        for (int t = 0; t < 8; ++t) {                 // k16 tiles over BK=128
            #pragma unroll
            for (int g = 0; g < 8; ++g) {             // n16 groups over d=128
                uint32_t vh4[4];
                ldsm4t(vh4, voff + t * (16 * RSB) + g * 32);
                mma_f16(o + 8 * g,     ph[t], vh4);
                mma_f16(o + 8 * g + 4, ph[t], vh4 + 2);
            }
        }

        // ---- V(kt) dead -> prefetch V(kt+1); covered by next QK ----
        __syncthreads();
        if (kt + 1 < nkt) copy34(sbase + SM_V, &g_v[bh][kt + 1][0], tid);
        CP_COMMIT();
    }

    // ---- epilogue: normalize, head_mask, store ----
    float li0 = hmv / L0, li1 = hmv / L1;
    float* o0 = out + ((size_t)bh * Sn + rg0) * Dh;
    float* o1 = o0 + 8 * Dh;
    #pragma unroll
    for (int n = 0; n < 16; ++n) {
        int c = 8 * n + c00;
        *reinterpret_cast<float2*>(o0 + c) = make_float2(o[4*n+0] * li0, o[4*n+1] * li0);
        *reinterpret_cast<float2*>(o1 + c) = make_float2(o[4*n+2] * li1, o[4*n+3] * li1);
    }
}

// ===================== launch =====================
extern "C" void kernel_launch(void* const* d_in, const int* in_sizes, int n_in,
                              void* d_out, int out_size)
{
    const float* q  = (const float*)d_in[0];
    const float* k  = (const float*)d_in[1];
    const float* v  = (const float*)d_in[2];
    const float* am = (const float*)d_in[3];
    const float* hm = (const float*)d_in[4];
    float* out = (float*)d_out;

    cudaFuncSetAttribute(fa_mma_kernel,
                         cudaFuncAttributeMaxDynamicSharedMemorySize, SM_TOTAL);

    prep_kernel<<<dim3(NKT, NBH), 128>>>(k, v);
    dim3 grid(Sn / BQ, NBH);   // (32 q-tiles, 32 bh)
    fa_mma_kernel<<<grid, NT, SM_TOTAL>>>(q, am, hm, out);
}